// round 1
// baseline (speedup 1.0000x reference)
#include <cuda_runtime.h>
#include <math.h>

#define DIM   128
#define AGGC  256   // concatenated agg width: [etype0 cols 0..127 | etype1 cols 128..255]

// ---------------- scratch (device globals; no allocation allowed) ----------------
__device__ int   g_deg [600000];
__device__ float g_norm[600000];
__device__ float g_agg_drug[100000ull * AGGC];  // 102.4 MB
__device__ float g_agg_gene[ 50000ull * AGGC];  //  51.2 MB

// ---------------- zero scratch ----------------
__global__ void zero_kernel() {
    size_t i = (size_t)blockIdx.x * blockDim.x + threadIdx.x;
    size_t stride = (size_t)gridDim.x * blockDim.x;
    float4 z = make_float4(0.f, 0.f, 0.f, 0.f);
    float4* a = (float4*)g_agg_drug;
    size_t na = 100000ull * (AGGC / 4);
    for (size_t j = i; j < na; j += stride) a[j] = z;
    float4* b = (float4*)g_agg_gene;
    size_t nb = 50000ull * (AGGC / 4);
    for (size_t j = i; j < nb; j += stride) b[j] = z;
    int4* d = (int4*)g_deg;
    for (size_t j = i; j < 600000 / 4; j += stride) d[j] = make_int4(0, 0, 0, 0);
}

// ---------------- degree counting ----------------
__global__ void deg_kernel(const int* __restrict__ src, const int* __restrict__ dst,
                           int offS, int offD, int n) {
    int i = blockIdx.x * blockDim.x + threadIdx.x;
    if (i < n) {
        atomicAdd(&g_deg[offS + src[i]], 1);
        atomicAdd(&g_deg[offD + dst[i]], 1);
    }
}

// ---------------- deg -> clip(deg,1)^-0.5 ----------------
__global__ void norm_kernel(int n) {
    int i = blockIdx.x * blockDim.x + threadIdx.x;
    if (i < n) g_norm[i] = rsqrtf(fmaxf((float)g_deg[i], 1.0f));
}

// ---------------- per-edge scatter: agg[dst, colOff..+127] += norm_src[s] * x[s, :] ----------------
// One warp per edge: 32 lanes x float4 = 128 floats. Vector f32 reduction (sm_90+).
__global__ void scatter_kernel(const float* __restrict__ x,
                               const int* __restrict__ src,
                               const int* __restrict__ dst,
                               int normOff,
                               float* __restrict__ agg,
                               int colOff, int nEdges) {
    int gw   = (blockIdx.x * blockDim.x + threadIdx.x) >> 5;
    int lane = threadIdx.x & 31;
    if (gw >= nEdges) return;
    int s = __ldg(src + gw);
    int d = __ldg(dst + gw);
    float w = __ldg(&g_norm[normOff + s]);
    float4 v = __ldg((const float4*)(x + (size_t)s * DIM) + lane);
    v.x *= w; v.y *= w; v.z *= w; v.w *= w;
    float* p = agg + (size_t)d * AGGC + colOff + lane * 4;
    asm volatile("red.global.add.v4.f32 [%0], {%1,%2,%3,%4};"
                 :: "l"(p), "f"(v.x), "f"(v.y), "f"(v.z), "f"(v.w) : "memory");
}

// ---------------- fused GEMM + bias + relu + L2-normalize ----------------
// out[r,:] = l2norm(relu( [n0[r]*agg[r,0:128] | n1[r]*agg[r,128:256]] @ [W0;W1] + bias ))
// Block: 256 threads = 16(tx: col groups) x 16(ty: row groups); M-tile = 64, full K=256, full N=128.
#define GEMM_SMEM ((256 * 128 + 256 * 68) * 4)  // W: 131072 B, A^T (pad 68): 69632 B -> 200704 B

__global__ void __launch_bounds__(256, 1)
gemm_kernel(const float* __restrict__ agg,
            const float* __restrict__ n0, const float* __restrict__ n1,
            const float* __restrict__ W0, const float* __restrict__ W1,
            const float* __restrict__ bias,
            float* __restrict__ out, int M) {
    extern __shared__ float sm[];
    float* Ws = sm;                // [256][128]
    float* As = sm + 256 * 128;    // [256][68]  (transposed A-tile, +4 pad -> 2-way max conflict)
    const int tid = threadIdx.x;

    // Load concatenated W into smem (row-major [k][c], k 0..127 from W0, 128..255 from W1)
    {
        const float4* w0 = (const float4*)W0;
        const float4* w1 = (const float4*)W1;
        float4* wsv = (float4*)Ws;
        #pragma unroll
        for (int i = tid; i < 8192; i += 256)
            wsv[i] = (i < 4096) ? __ldg(w0 + i) : __ldg(w1 + i - 4096);
    }

    // Load A-tile (64 rows x 256 K), scale halves by n0/n1, store transposed.
    const int rowBase = blockIdx.x * 64;
    for (int l = tid; l < 4096; l += 256) {
        int kq = l & 63;      // float4 index along K -> coalesced
        int r  = l >> 6;
        int gr = rowBase + r;
        float4 v = make_float4(0.f, 0.f, 0.f, 0.f);
        if (gr < M) {
            v = __ldg((const float4*)(agg + (size_t)gr * AGGC) + kq);
            float s = (kq < 32) ? __ldg(n0 + gr) : __ldg(n1 + gr);
            v.x *= s; v.y *= s; v.z *= s; v.w *= s;
        }
        int k = kq << 2;
        As[(k + 0) * 68 + r] = v.x;
        As[(k + 1) * 68 + r] = v.y;
        As[(k + 2) * 68 + r] = v.z;
        As[(k + 3) * 68 + r] = v.w;
    }
    __syncthreads();

    const int tx = tid & 15, ty = tid >> 4;
    const int c0 = tx * 8, r0 = ty * 4;

    float acc[4][8];
    #pragma unroll
    for (int i = 0; i < 4; i++)
        #pragma unroll
        for (int j = 0; j < 8; j++) acc[i][j] = 0.f;

    #pragma unroll 8
    for (int k = 0; k < 256; k++) {
        float4 a  = *(const float4*)&As[k * 68 + r0];
        float4 b0 = *(const float4*)&Ws[k * 128 + c0];
        float4 b1 = *(const float4*)&Ws[k * 128 + c0 + 4];
        float av[4] = {a.x, a.y, a.z, a.w};
        float bv[8] = {b0.x, b0.y, b0.z, b0.w, b1.x, b1.y, b1.z, b1.w};
        #pragma unroll
        for (int i = 0; i < 4; i++)
            #pragma unroll
            for (int j = 0; j < 8; j++)
                acc[i][j] = fmaf(av[i], bv[j], acc[i][j]);
    }

    float bb[8];
    #pragma unroll
    for (int j = 0; j < 8; j++) bb[j] = __ldg(bias + c0 + j);

    // Epilogue: relu(h+bias), row L2 norm via 16-lane xor-shuffle (tx group), write.
    #pragma unroll
    for (int i = 0; i < 4; i++) {
        int gr = rowBase + r0 + i;
        float h[8]; float ss = 0.f;
        #pragma unroll
        for (int j = 0; j < 8; j++) {
            h[j] = fmaxf(acc[i][j] + bb[j], 0.f);
            ss += h[j] * h[j];
        }
        #pragma unroll
        for (int off = 8; off > 0; off >>= 1)
            ss += __shfl_xor_sync(0xffffffffu, ss, off);   // stays within 16-lane ty-group
        if (gr < M) {
            float inv = 1.0f / fmaxf(sqrtf(ss), 1e-12f);
            float4 o0 = make_float4(h[0]*inv, h[1]*inv, h[2]*inv, h[3]*inv);
            float4 o1 = make_float4(h[4]*inv, h[5]*inv, h[6]*inv, h[7]*inv);
            *(float4*)(out + (size_t)gr * DIM + c0)     = o0;
            *(float4*)(out + (size_t)gr * DIM + c0 + 4) = o1;
        }
    }
}

// ---------------- launch ----------------
extern "C" void kernel_launch(void* const* d_in, const int* in_sizes, int n_in,
                              void* d_out, int out_size) {
    const float* x_drug = (const float*)d_in[0];
    const float* x_gene = (const float*)d_in[1];
    const float* W_dd   = (const float*)d_in[2];
    const float* W_dg   = (const float*)d_in[3];
    const float* W_gd   = (const float*)d_in[4];
    const float* W_gg   = (const float*)d_in[5];
    const float* h_bias = (const float*)d_in[6];
    const int* src_dd = (const int*)d_in[7];   const int* dst_dd = (const int*)d_in[8];
    const int* src_dg = (const int*)d_in[9];   const int* dst_dg = (const int*)d_in[10];
    const int* src_gd = (const int*)d_in[11];  const int* dst_gd = (const int*)d_in[12];
    const int* src_gg = (const int*)d_in[13];  const int* dst_gg = (const int*)d_in[14];
    float* out = (float*)d_out;

    const int E     = in_sizes[7];
    const int nDrug = in_sizes[0] / DIM;
    const int nGene = in_sizes[1] / DIM;

    // norm/deg segment offsets
    const int o_dd_s = 0;
    const int o_dd_d = o_dd_s + nDrug;
    const int o_dg_s = o_dd_d + nDrug;
    const int o_dg_d = o_dg_s + nDrug;
    const int o_gd_s = o_dg_d + nGene;
    const int o_gd_d = o_gd_s + nGene;
    const int o_gg_s = o_gd_d + nDrug;
    const int o_gg_d = o_gg_s + nGene;
    const int nTot   = o_gg_d + nGene;   // = 600000

    float *aggD, *aggG, *normP;
    cudaGetSymbolAddress((void**)&aggD,  g_agg_drug);
    cudaGetSymbolAddress((void**)&aggG,  g_agg_gene);
    cudaGetSymbolAddress((void**)&normP, g_norm);

    zero_kernel<<<2048, 256>>>();

    const int degBlocks = (E + 255) / 256;
    deg_kernel<<<degBlocks, 256>>>(src_dd, dst_dd, o_dd_s, o_dd_d, E);
    deg_kernel<<<degBlocks, 256>>>(src_dg, dst_dg, o_dg_s, o_dg_d, E);
    deg_kernel<<<degBlocks, 256>>>(src_gd, dst_gd, o_gd_s, o_gd_d, E);
    deg_kernel<<<degBlocks, 256>>>(src_gg, dst_gg, o_gg_s, o_gg_d, E);

    norm_kernel<<<(nTot + 255) / 256, 256>>>(nTot);

    // one etype at a time -> each (x_src + agg-half) working set stays L2-resident
    const int scBlocks = (int)(((long long)E * 32 + 255) / 256);
    scatter_kernel<<<scBlocks, 256>>>(x_drug, src_dd, dst_dd, o_dd_s, aggD, 0,   E);
    scatter_kernel<<<scBlocks, 256>>>(x_gene, src_gd, dst_gd, o_gd_s, aggD, 128, E);
    scatter_kernel<<<scBlocks, 256>>>(x_drug, src_dg, dst_dg, o_dg_s, aggG, 0,   E);
    scatter_kernel<<<scBlocks, 256>>>(x_gene, src_gg, dst_gg, o_gg_s, aggG, 128, E);

    cudaFuncSetAttribute(gemm_kernel, cudaFuncAttributeMaxDynamicSharedMemorySize, GEMM_SMEM);
    gemm_kernel<<<(nDrug + 63) / 64, 256, GEMM_SMEM>>>(
        aggD, normP + o_dd_d, normP + o_gd_d, W_dd, W_gd, h_bias, out, nDrug);
    gemm_kernel<<<(nGene + 63) / 64, 256, GEMM_SMEM>>>(
        aggG, normP + o_dg_d, normP + o_gg_d, W_dg, W_gg, h_bias,
        out + (size_t)nDrug * DIM, nGene);
}

// round 3
// speedup vs baseline: 1.2715x; 1.2715x over previous
#include <cuda_runtime.h>
#include <cstdint>
#include <math.h>
#include <mma.h>

using namespace nvcuda;

#define DIM   128
#define AGGC  256   // concatenated agg width: [etype0 cols 0..127 | etype1 cols 128..255]

// ---------------- scratch (device globals; no allocation allowed) ----------------
__device__ int   g_deg [600000];
__device__ float g_norm[600000];
__device__ float g_agg_drug[100000ull * AGGC];  // 102.4 MB
__device__ float g_agg_gene[ 50000ull * AGGC];  //  51.2 MB

// ---------------- zero scratch ----------------
__global__ void zero_kernel() {
    size_t i = (size_t)blockIdx.x * blockDim.x + threadIdx.x;
    size_t stride = (size_t)gridDim.x * blockDim.x;
    float4 z = make_float4(0.f, 0.f, 0.f, 0.f);
    float4* a = (float4*)g_agg_drug;
    size_t na = 100000ull * (AGGC / 4);
    for (size_t j = i; j < na; j += stride) a[j] = z;
    float4* b = (float4*)g_agg_gene;
    size_t nb = 50000ull * (AGGC / 4);
    for (size_t j = i; j < nb; j += stride) b[j] = z;
    int4* d = (int4*)g_deg;
    for (size_t j = i; j < 600000 / 4; j += stride) d[j] = make_int4(0, 0, 0, 0);
}

// ---------------- degree counting (all 4 etypes, one launch) ----------------
__global__ void deg_all(const int* __restrict__ s0, const int* __restrict__ d0, int o0s, int o0d,
                        const int* __restrict__ s1, const int* __restrict__ d1, int o1s, int o1d,
                        const int* __restrict__ s2, const int* __restrict__ d2, int o2s, int o2d,
                        const int* __restrict__ s3, const int* __restrict__ d3, int o3s, int o3d,
                        int E) {
    int i = blockIdx.x * blockDim.x + threadIdx.x;
    const int *s, *d; int os, od, j;
    if (i < E)          { s = s0; d = d0; os = o0s; od = o0d; j = i; }
    else if (i < 2 * E) { s = s1; d = d1; os = o1s; od = o1d; j = i - E; }
    else if (i < 3 * E) { s = s2; d = d2; os = o2s; od = o2d; j = i - 2 * E; }
    else if (i < 4 * E) { s = s3; d = d3; os = o3s; od = o3d; j = i - 3 * E; }
    else return;
    atomicAdd(&g_deg[os + __ldg(s + j)], 1);
    atomicAdd(&g_deg[od + __ldg(d + j)], 1);
}

// ---------------- deg -> clip(deg,1)^-0.5 ----------------
__global__ void norm_kernel(int n) {
    int i = blockIdx.x * blockDim.x + threadIdx.x;
    if (i < n) g_norm[i] = rsqrtf(fmaxf((float)g_deg[i], 1.0f));
}

// ---------------- per-edge scatter: agg[dst, colOff..+127] += norm_src[s] * x[s, :] ----------------
__global__ void scatter_kernel(const float* __restrict__ x,
                               const int* __restrict__ src,
                               const int* __restrict__ dst,
                               int normOff,
                               float* __restrict__ agg,
                               int colOff, int nEdges) {
    int gw   = (blockIdx.x * blockDim.x + threadIdx.x) >> 5;
    int lane = threadIdx.x & 31;
    if (gw >= nEdges) return;
    int s = __ldg(src + gw);
    int d = __ldg(dst + gw);
    float w = __ldg(&g_norm[normOff + s]);
    float4 v = __ldg((const float4*)(x + (size_t)s * DIM) + lane);
    v.x *= w; v.y *= w; v.z *= w; v.w *= w;
    float* p = agg + (size_t)d * AGGC + colOff + lane * 4;
    asm volatile("red.global.add.v4.f32 [%0], {%1,%2,%3,%4};"
                 :: "l"(p), "f"(v.x), "f"(v.y), "f"(v.z), "f"(v.w) : "memory");
}

// ---------------- WMMA tf32 GEMM + bias + relu + L2-normalize ----------------
// out[r,:] = l2norm(relu( [n0[r]*agg[r,0:128] | n1[r]*agg[r,128:256]] @ [W0;W1] + bias ))
// CTA tile: M=128, N=128, K=256 (A chunked in 2 x K=128). 256 threads = 8 warps,
// each warp: 16 rows x 128 cols = 8 wmma tiles (m16n16k8), 32 k-steps.
#define APAD 132
#define BPAD 132
#define GEMM_SMEM ((256 * BPAD + 128 * APAD + 128) * 4)   // B:135168 A:67584 bias:512 = 203264 B

__global__ void __launch_bounds__(256, 1)
gemm_wmma(const float* __restrict__ agg,
          const float* __restrict__ n0, const float* __restrict__ n1,
          const float* __restrict__ W0, const float* __restrict__ W1,
          const float* __restrict__ bias,
          float* __restrict__ out, int M) {
    extern __shared__ float sm[];
    float* Bs = sm;                          // [256][BPAD]  Wcat (k-major)
    float* As = sm + 256 * BPAD;             // [128][APAD]  scaled A chunk (also C scratch)
    float* bs = sm + 256 * BPAD + 128 * APAD; // [128] bias
    const int tid = threadIdx.x, wid = tid >> 5, lane = tid & 31;

    if (tid < 128) bs[tid] = __ldg(bias + tid);

    // Stage Wcat[k][n]: k<128 from W0, else W1. Coalesced over n; tf32-round once.
    for (int i = tid; i < 256 * 128; i += 256) {
        int k = i >> 7, n = i & 127;
        float v = (k < 128) ? __ldg(W0 + k * 128 + n) : __ldg(W1 + (k - 128) * 128 + n);
        Bs[k * BPAD + n] = wmma::__float_to_tf32(v);
    }

    const int rowBase = blockIdx.x * 128;
    const int wrow = wid * 16;

    wmma::fragment<wmma::accumulator, 16, 16, 8, float> c[8];
    #pragma unroll
    for (int t = 0; t < 8; t++) wmma::fill_fragment(c[t], 0.0f);

    for (int kc = 0; kc < 2; kc++) {
        __syncthreads();   // As free (prev chunk consumed / first entry); Bs ready after 1st
        const float* nrm = kc ? n1 : n0;
        // Stage A chunk [128 rows x 128 k], scaled by norm, tf32-rounded.
        for (int i = tid; i < 4096; i += 256) {           // float4 granularity
            int m = i >> 5, kq = i & 31;
            int gr = rowBase + m;
            float4 v = make_float4(0.f, 0.f, 0.f, 0.f);
            if (gr < M) {
                v = __ldg((const float4*)(agg + (size_t)gr * AGGC) + kc * 32 + kq);
                float s = __ldg(nrm + gr);
                v.x *= s; v.y *= s; v.z *= s; v.w *= s;
            }
            float* p = &As[m * APAD + kq * 4];
            p[0] = wmma::__float_to_tf32(v.x);
            p[1] = wmma::__float_to_tf32(v.y);
            p[2] = wmma::__float_to_tf32(v.z);
            p[3] = wmma::__float_to_tf32(v.w);
        }
        __syncthreads();

        #pragma unroll
        for (int ks = 0; ks < 16; ks++) {
            wmma::fragment<wmma::matrix_a, 16, 16, 8, wmma::precision::tf32, wmma::row_major> a;
            wmma::load_matrix_sync(a, &As[wrow * APAD + ks * 8], APAD);
            #pragma unroll
            for (int t = 0; t < 8; t++) {
                wmma::fragment<wmma::matrix_b, 16, 16, 8, wmma::precision::tf32, wmma::row_major> b;
                wmma::load_matrix_sync(b, &Bs[(kc * 128 + ks * 8) * BPAD + t * 16], BPAD);
                wmma::mma_sync(c[t], a, b, c[t]);
            }
        }
    }
    __syncthreads();

    // Epilogue: dump C to smem (reuse As region; 16 x APAD per warp), then
    // per-row relu(+bias) + L2 normalize. 2 lanes per row (64 cols each).
    float* Cw = As + wrow * APAD;
    #pragma unroll
    for (int t = 0; t < 8; t++)
        wmma::store_matrix_sync(&Cw[t * 16], c[t], APAD, wmma::mem_row_major);
    __syncwarp();

    const int r = lane >> 1, half = lane & 1;
    const int gr = rowBase + wrow + r;
    const float* crow = &Cw[r * APAD + half * 64];
    const float* brow = &bs[half * 64];

    float ss = 0.f;
    #pragma unroll
    for (int j = 0; j < 64; j++) {
        float v = fmaxf(crow[j] + brow[j], 0.f);
        ss += v * v;
    }
    ss += __shfl_xor_sync(0xffffffffu, ss, 1);
    float inv = 1.0f / fmaxf(sqrtf(ss), 1e-12f);

    if (gr < M) {
        float4* op = (float4*)(out + (size_t)gr * DIM + half * 64);
        #pragma unroll
        for (int q = 0; q < 16; q++) {
            float4 o;
            o.x = fmaxf(crow[q * 4 + 0] + brow[q * 4 + 0], 0.f) * inv;
            o.y = fmaxf(crow[q * 4 + 1] + brow[q * 4 + 1], 0.f) * inv;
            o.z = fmaxf(crow[q * 4 + 2] + brow[q * 4 + 2], 0.f) * inv;
            o.w = fmaxf(crow[q * 4 + 3] + brow[q * 4 + 3], 0.f) * inv;
            op[q] = o;
        }
    }
}

// ---------------- launch ----------------
extern "C" void kernel_launch(void* const* d_in, const int* in_sizes, int n_in,
                              void* d_out, int out_size) {
    const float* x_drug = (const float*)d_in[0];
    const float* x_gene = (const float*)d_in[1];
    const float* W_dd   = (const float*)d_in[2];
    const float* W_dg   = (const float*)d_in[3];
    const float* W_gd   = (const float*)d_in[4];
    const float* W_gg   = (const float*)d_in[5];
    const float* h_bias = (const float*)d_in[6];
    const int* src_dd = (const int*)d_in[7];   const int* dst_dd = (const int*)d_in[8];
    const int* src_dg = (const int*)d_in[9];   const int* dst_dg = (const int*)d_in[10];
    const int* src_gd = (const int*)d_in[11];  const int* dst_gd = (const int*)d_in[12];
    const int* src_gg = (const int*)d_in[13];  const int* dst_gg = (const int*)d_in[14];
    float* out = (float*)d_out;

    const int E     = in_sizes[7];
    const int nDrug = in_sizes[0] / DIM;
    const int nGene = in_sizes[1] / DIM;

    // norm/deg segment offsets
    const int o_dd_s = 0;
    const int o_dd_d = o_dd_s + nDrug;
    const int o_dg_s = o_dd_d + nDrug;
    const int o_dg_d = o_dg_s + nDrug;
    const int o_gd_s = o_dg_d + nGene;
    const int o_gd_d = o_gd_s + nGene;
    const int o_gg_s = o_gd_d + nDrug;
    const int o_gg_d = o_gg_s + nGene;
    const int nTot   = o_gg_d + nGene;   // = 600000

    float *aggD, *aggG, *normP;
    cudaGetSymbolAddress((void**)&aggD,  g_agg_drug);
    cudaGetSymbolAddress((void**)&aggG,  g_agg_gene);
    cudaGetSymbolAddress((void**)&normP, g_norm);

    zero_kernel<<<2048, 256>>>();

    const long long totDeg = 4LL * E;
    deg_all<<<(int)((totDeg + 255) / 256), 256>>>(
        src_dd, dst_dd, o_dd_s, o_dd_d,
        src_dg, dst_dg, o_dg_s, o_dg_d,
        src_gd, dst_gd, o_gd_s, o_gd_d,
        src_gg, dst_gg, o_gg_s, o_gg_d, E);

    norm_kernel<<<(nTot + 255) / 256, 256>>>(nTot);

    // one etype at a time -> working sets stay L2-resident
    const int scBlocks = (int)(((long long)E * 32 + 255) / 256);
    scatter_kernel<<<scBlocks, 256>>>(x_drug, src_dd, dst_dd, o_dd_s, aggD, 0,   E);
    scatter_kernel<<<scBlocks, 256>>>(x_gene, src_gd, dst_gd, o_gd_s, aggD, 128, E);
    scatter_kernel<<<scBlocks, 256>>>(x_drug, src_dg, dst_dg, o_dg_s, aggG, 0,   E);
    scatter_kernel<<<scBlocks, 256>>>(x_gene, src_gg, dst_gg, o_gg_s, aggG, 128, E);

    cudaFuncSetAttribute(gemm_wmma, cudaFuncAttributeMaxDynamicSharedMemorySize, GEMM_SMEM);
    gemm_wmma<<<(nDrug + 127) / 128, 256, GEMM_SMEM>>>(
        aggD, normP + o_dd_d, normP + o_gd_d, W_dd, W_gd, h_bias, out, nDrug);
    gemm_wmma<<<(nGene + 127) / 128, 256, GEMM_SMEM>>>(
        aggG, normP + o_dg_d, normP + o_gg_d, W_dg, W_gg, h_bias,
        out + (size_t)nDrug * DIM, nGene);
}